// round 15
// baseline (speedup 1.0000x reference)
#include <cuda_runtime.h>
#include <cuda_bf16.h>
#include <cstdint>

// TemplatePointwiseAttention, folded-weight + tensor-core formulation.
//   M[i][h*64+j] = (1/8) * sum_c Wq[i][h*64+c] * Wk[j][h*64+c]   (128 x 256)
//   N[h*64+j][o] =          sum_c Wv[j][h*64+c] * Wo[h*64+c][o]  (256 x 128)
//   K1: u = z@M (tf32 mma) ; logits/softmax/s in fp32 ; S -> gmem
//   K2: out = S@N + bo (bf16 hi/lo 3-term mma)

#define R 384
#define NP (R*R)
#define CZ 128
#define HC 256
#define NT 4
#define PB 32
#define NTILES (NP/PB)              // 4608
#define TILES_PER_CTA 8
#define GRID1 (NTILES/TILES_PER_CTA) // 576

// smem pitches (floats / u32), chosen conflict-free for fragment access
#define MP  264   // M  [128][264] f32(tf32)
#define ZPP 132   // z  [32][132]  f32(tf32)
#define TTP 257   // t  [32][257]  f32
#define UP  260   // u  [32][260]  f32
#define NPP 136   // Npacked [128][136] u32 (bf16x2)
#define SPP 264   // s  [32][264]  f32

__device__ float g_M[CZ*HC];
__device__ float g_N[HC*CZ];
__device__ float g_S[(size_t)NP*HC];

// ---------------------------------------------------------------------------
__device__ __forceinline__ uint32_t f2tf32(float x) {
    uint32_t r;
    asm("cvt.rna.tf32.f32 %0, %1;" : "=r"(r) : "f"(x));
    return r;
}

__device__ __forceinline__ void mma_tf32(float c[4], uint32_t a0, uint32_t a1,
                                         uint32_t a2, uint32_t a3,
                                         uint32_t b0, uint32_t b1) {
    asm volatile(
        "mma.sync.aligned.m16n8k8.row.col.f32.tf32.tf32.f32 "
        "{%0,%1,%2,%3}, {%4,%5,%6,%7}, {%8,%9}, {%0,%1,%2,%3};"
        : "+f"(c[0]), "+f"(c[1]), "+f"(c[2]), "+f"(c[3])
        : "r"(a0), "r"(a1), "r"(a2), "r"(a3), "r"(b0), "r"(b1));
}

__device__ __forceinline__ void mma_bf16(float c[4], uint32_t a0, uint32_t a1,
                                         uint32_t a2, uint32_t a3,
                                         uint32_t b0, uint32_t b1) {
    asm volatile(
        "mma.sync.aligned.m16n8k16.row.col.f32.bf16.bf16.f32 "
        "{%0,%1,%2,%3}, {%4,%5,%6,%7}, {%8,%9}, {%0,%1,%2,%3};"
        : "+f"(c[0]), "+f"(c[1]), "+f"(c[2]), "+f"(c[3])
        : "r"(a0), "r"(a1), "r"(a2), "r"(a3), "r"(b0), "r"(b1));
}

__device__ __forceinline__ uint32_t pack_bf2(float lo_elem, float hi_elem) {
    __nv_bfloat162 h = __floats2bfloat162_rn(lo_elem, hi_elem); // .x -> low 16
    return *reinterpret_cast<uint32_t*>(&h);
}

// ---------------------------------------------------------------------------
// K0: fold weights (unchanged from R1 — correct & cheap)
// ---------------------------------------------------------------------------
__global__ void fold_k(const float* __restrict__ Wq, const float* __restrict__ Wk,
                       const float* __restrict__ Wv, const float* __restrict__ Wo) {
    int idx = blockIdx.x * 256 + threadIdx.x;
    if (idx < CZ*HC) {
        int i = idx >> 8, hc = idx & 255;
        int h = hc >> 6, j = hc & 63;
        const float* wq = Wq + i*HC + h*64;
        const float* wk = Wk + j*HC + h*64;
        float a = 0.f;
        #pragma unroll
        for (int c = 0; c < 64; c++) a += wq[c] * wk[c];
        g_M[idx] = a * 0.125f;
    } else {
        int idx2 = idx - CZ*HC;
        int jh = idx2 >> 7, o = idx2 & 127;
        int h = jh >> 6, j = jh & 63;
        const float* wv = Wv + j*HC + h*64;
        const float* wo = Wo + (h*64)*CZ + o;
        float a = 0.f;
        #pragma unroll
        for (int c = 0; c < 64; c++) a += wv[c] * wo[c*CZ];
        g_N[idx2] = a;
    }
}

// ---------------------------------------------------------------------------
// K1: u = z @ M via tf32 mma ; softmax ; s -> g_S
// 256 threads = 8 warps: warp tile 16(m) x 64(n); warps 2(m) x 4(n).
// ---------------------------------------------------------------------------
__global__ __launch_bounds__(256, 1) void attn_k1(const float* __restrict__ z2d,
                                                  const float* __restrict__ t2d) {
    extern __shared__ float sm[];
    float* Ms = sm;                    // 128*264
    float* zs = Ms + CZ*MP;            // 32*132
    float* tt = zs + PB*ZPP;           // 32*257
    float* us = tt + PB*TTP;           // 32*260
    float* ws = us + PB*UP;            // 32*16
    const int tid = threadIdx.x;
    const int warp = tid >> 5, lane = tid & 31;
    const int g = lane >> 2, tig = lane & 3;
    const int wm = warp & 1, wn = warp >> 1;

    // stationary M (tf32-rounded)
    for (int k = tid; k < CZ*HC; k += 256) {
        int i = k >> 8, n = k & 255;
        Ms[i*MP + n] = __uint_as_float(f2tf32(g_M[k]));
    }

    for (int tl = 0; tl < TILES_PER_CTA; ++tl) {
        const int p0 = (blockIdx.x * TILES_PER_CTA + tl) * PB;

        // z tile (tf32-rounded), [p][i]
        for (int k = tid; k < PB*CZ; k += 256) {
            int p = k >> 7, i = k & 127;
            zs[p*ZPP + i] = __uint_as_float(f2tf32(z2d[(size_t)(p0 + p)*CZ + i]));
        }
        // template tile fp32: tt[p][t*64+j]
        for (int k = tid; k < PB*NT*64; k += 256) {
            int p = k >> 8, rem = k & 255;
            tt[p*TTP + rem] = t2d[((size_t)(rem >> 6)*NP + (p0 + p))*64 + (rem & 63)];
        }
        __syncthreads();

        // GEMM1: u[32][256] = z[32][128] @ M[128][256]
        float c[8][4];
        #pragma unroll
        for (int n8 = 0; n8 < 8; n8++)
            #pragma unroll
            for (int q = 0; q < 4; q++) c[n8][q] = 0.f;

        #pragma unroll
        for (int k8 = 0; k8 < 16; k8++) {
            const int k0 = k8 * 8;
            const int r0 = wm*16 + g;
            uint32_t a0 = __float_as_uint(zs[r0*ZPP + k0 + tig]);
            uint32_t a1 = __float_as_uint(zs[(r0+8)*ZPP + k0 + tig]);
            uint32_t a2 = __float_as_uint(zs[r0*ZPP + k0 + tig + 4]);
            uint32_t a3 = __float_as_uint(zs[(r0+8)*ZPP + k0 + tig + 4]);
            #pragma unroll
            for (int n8 = 0; n8 < 8; n8++) {
                const int n = wn*64 + n8*8 + g;
                uint32_t b0 = __float_as_uint(Ms[(k0 + tig)*MP + n]);
                uint32_t b1 = __float_as_uint(Ms[(k0 + tig + 4)*MP + n]);
                mma_tf32(c[n8], a0, a1, a2, a3, b0, b1);
            }
        }
        // store u fragments
        {
            const int r0 = wm*16 + g;
            #pragma unroll
            for (int n8 = 0; n8 < 8; n8++) {
                const int ncol = wn*64 + n8*8 + 2*tig;
                *(float2*)(us + r0*UP + ncol)     = make_float2(c[n8][0], c[n8][1]);
                *(float2*)(us + (r0+8)*UP + ncol) = make_float2(c[n8][2], c[n8][3]);
            }
        }
        __syncthreads();

        // logits + softmax (fp32 exact)
        if (tid < 128) {
            int h = tid >> 5, p = tid & 31;
            const float* up = us + p*UP + h*64;
            float lg[NT];
            #pragma unroll
            for (int t = 0; t < NT; t++) {
                const float* tp = tt + p*TTP + t*64;
                float a = 0.f;
                #pragma unroll
                for (int jj = 0; jj < 64; jj++) a += up[jj] * tp[jj];
                lg[t] = a;
            }
            float mx = fmaxf(fmaxf(lg[0], lg[1]), fmaxf(lg[2], lg[3]));
            float e0 = __expf(lg[0]-mx), e1 = __expf(lg[1]-mx);
            float e2 = __expf(lg[2]-mx), e3 = __expf(lg[3]-mx);
            float inv = 1.f / (e0 + e1 + e2 + e3);
            float* wp = ws + p*16 + h*4;
            wp[0] = e0*inv; wp[1] = e1*inv; wp[2] = e2*inv; wp[3] = e3*inv;
        }
        __syncthreads();

        // s (fp32 exact) -> g_S
        {
            const int h = tid >> 6, jj = tid & 63;
            #pragma unroll 4
            for (int p = 0; p < PB; p++) {
                const float* wp = ws + p*16 + h*4;
                const float* tp = tt + p*TTP + jj;
                float s = wp[0]*tp[0] + wp[1]*tp[64] + wp[2]*tp[128] + wp[3]*tp[192];
                g_S[(size_t)(p0 + p)*HC + tid] = s;
            }
        }
        __syncthreads();
    }
}

// ---------------------------------------------------------------------------
// K2: out = S @ N + bo via bf16 hi/lo (3 mma terms).
// 256 threads = 8 warps: warp tile 16(m) x 32(n); warps 2(m) x 4(n).
// N packed in smem as bf16x2 pairs along k: Npk[k/2][o].
// ---------------------------------------------------------------------------
__global__ __launch_bounds__(256, 1) void attn_k2(const float* __restrict__ bo,
                                                  float* __restrict__ out) {
    extern __shared__ float sm[];
    uint32_t* Nhi = (uint32_t*)sm;          // [128][136] u32
    uint32_t* Nlo = Nhi + 128*NPP;          // [128][136] u32
    float*    ss  = (float*)(Nlo + 128*NPP); // [32][264]
    const int tid = threadIdx.x;
    const int warp = tid >> 5, lane = tid & 31;
    const int g = lane >> 2, tig = lane & 3;
    const int wm = warp & 1, wn = warp >> 1;

    // stationary N, split+packed
    for (int k = tid; k < 128*CZ; k += 256) {
        int k2 = k >> 7, o = k & 127;
        float v0 = g_N[(size_t)(2*k2)*CZ + o];
        float v1 = g_N[(size_t)(2*k2 + 1)*CZ + o];
        float h0 = __bfloat162float(__float2bfloat16_rn(v0));
        float h1 = __bfloat162float(__float2bfloat16_rn(v1));
        Nhi[k2*NPP + o] = pack_bf2(h0, h1);
        Nlo[k2*NPP + o] = pack_bf2(v0 - h0, v1 - h1);
    }

    // per-thread bias for output columns
    float bias[4][2];
    #pragma unroll
    for (int n8 = 0; n8 < 4; n8++) {
        int ncol = wn*32 + n8*8 + 2*tig;
        bias[n8][0] = __ldg(bo + ncol);
        bias[n8][1] = __ldg(bo + ncol + 1);
    }

    for (int tl = 0; tl < TILES_PER_CTA; ++tl) {
        const int p0 = (blockIdx.x * TILES_PER_CTA + tl) * PB;
        for (int k = tid; k < PB*HC; k += 256) {
            int p = k >> 8, j = k & 255;
            ss[p*SPP + j] = g_S[(size_t)(p0 + p)*HC + j];
        }
        __syncthreads();

        float c[4][4];
        #pragma unroll
        for (int n8 = 0; n8 < 4; n8++)
            #pragma unroll
            for (int q = 0; q < 4; q++) c[n8][q] = 0.f;

        #pragma unroll
        for (int k16 = 0; k16 < 16; k16++) {
            const int k0 = k16 * 16;
            const int r0 = wm*16 + g;
            // A build: fp32 s -> bf16 hi/lo fragments
            float2 v00 = *(const float2*)(ss + r0*SPP + k0 + 2*tig);
            float2 v02 = *(const float2*)(ss + r0*SPP + k0 + 2*tig + 8);
            float2 v10 = *(const float2*)(ss + (r0+8)*SPP + k0 + 2*tig);
            float2 v12 = *(const float2*)(ss + (r0+8)*SPP + k0 + 2*tig + 8);
            float h00x = __bfloat162float(__float2bfloat16_rn(v00.x));
            float h00y = __bfloat162float(__float2bfloat16_rn(v00.y));
            float h02x = __bfloat162float(__float2bfloat16_rn(v02.x));
            float h02y = __bfloat162float(__float2bfloat16_rn(v02.y));
            float h10x = __bfloat162float(__float2bfloat16_rn(v10.x));
            float h10y = __bfloat162float(__float2bfloat16_rn(v10.y));
            float h12x = __bfloat162float(__float2bfloat16_rn(v12.x));
            float h12y = __bfloat162float(__float2bfloat16_rn(v12.y));
            uint32_t ah0 = pack_bf2(h00x, h00y);
            uint32_t ah1 = pack_bf2(h10x, h10y);
            uint32_t ah2 = pack_bf2(h02x, h02y);
            uint32_t ah3 = pack_bf2(h12x, h12y);
            uint32_t al0 = pack_bf2(v00.x - h00x, v00.y - h00y);
            uint32_t al1 = pack_bf2(v10.x - h10x, v10.y - h10y);
            uint32_t al2 = pack_bf2(v02.x - h02x, v02.y - h02y);
            uint32_t al3 = pack_bf2(v12.x - h12x, v12.y - h12y);

            const int kr = k0 / 2;   // packed row base
            #pragma unroll
            for (int n8 = 0; n8 < 4; n8++) {
                const int n = wn*32 + n8*8 + g;
                uint32_t bh0 = Nhi[(kr + tig)*NPP + n];
                uint32_t bh1 = Nhi[(kr + tig + 4)*NPP + n];
                uint32_t bl0 = Nlo[(kr + tig)*NPP + n];
                uint32_t bl1 = Nlo[(kr + tig + 4)*NPP + n];
                mma_bf16(c[n8], ah0, ah1, ah2, ah3, bh0, bh1); // s_hi * N_hi
                mma_bf16(c[n8], ah0, ah1, ah2, ah3, bl0, bl1); // s_hi * N_lo
                mma_bf16(c[n8], al0, al1, al2, al3, bh0, bh1); // s_lo * N_hi
            }
        }

        // epilogue: +bias, store
        {
            const int r0 = wm*16 + g;
            #pragma unroll
            for (int n8 = 0; n8 < 4; n8++) {
                const int ncol = wn*32 + n8*8 + 2*tig;
                *(float2*)(out + (size_t)(p0 + r0)*CZ + ncol) =
                    make_float2(c[n8][0] + bias[n8][0], c[n8][1] + bias[n8][1]);
                *(float2*)(out + (size_t)(p0 + r0 + 8)*CZ + ncol) =
                    make_float2(c[n8][2] + bias[n8][0], c[n8][3] + bias[n8][1]);
            }
        }
        __syncthreads();
    }
}

// ---------------------------------------------------------------------------
extern "C" void kernel_launch(void* const* d_in, const int* in_sizes, int n_in,
                              void* d_out, int out_size) {
    const float* z2d = (const float*)d_in[0];
    const float* t2d = (const float*)d_in[1];
    const float* Wq  = (const float*)d_in[2];
    const float* Wk  = (const float*)d_in[3];
    const float* Wv  = (const float*)d_in[4];
    const float* Wo  = (const float*)d_in[5];
    const float* Wo2 = (const float*)d_in[5];
    const float* bo  = (const float*)d_in[6];
    (void)Wo2;
    float* out = (float*)d_out;

    const size_t sm1 = (size_t)(CZ*MP + PB*ZPP + PB*TTP + PB*UP + PB*16) * sizeof(float);
    const size_t sm2 = (size_t)(128*NPP*2) * sizeof(uint32_t) + (size_t)(PB*SPP) * sizeof(float);
    cudaFuncSetAttribute(attn_k1, cudaFuncAttributeMaxDynamicSharedMemorySize, (int)sm1);
    cudaFuncSetAttribute(attn_k2, cudaFuncAttributeMaxDynamicSharedMemorySize, (int)sm2);

    fold_k<<<256, 256>>>(Wq, Wk, Wv, Wo);
    attn_k1<<<GRID1, 256, sm1>>>(z2d, t2d);
    attn_k2<<<GRID1, 256, sm2>>>(bo, out);
}

// round 16
// speedup vs baseline: 1.0025x; 1.0025x over previous
#include <cuda_runtime.h>
#include <cuda_bf16.h>
#include <cstdint>

// TemplatePointwiseAttention, folded-weight + tensor-core formulation.
//   M[i][h*64+j] = (1/8) * sum_c Wq[i][h*64+c] * Wk[j][h*64+c]   (128 x 256)
//   N[h*64+j][o] =          sum_c Wv[j][h*64+c] * Wo[h*64+c][o]  (256 x 128)
//   K1: u = z@M (tf32 mma) ; logits/softmax/s in fp32 ; S -> gmem
//   K2: out = S@N + bo (bf16 hi/lo 3-term mma)

#define R 384
#define NP (R*R)
#define CZ 128
#define HC 256
#define NT 4
#define PB 32
#define NTILES (NP/PB)              // 4608
#define TILES_PER_CTA 8
#define GRID1 (NTILES/TILES_PER_CTA) // 576

// smem pitches (floats / u32), chosen conflict-free for fragment access
#define MP  264   // M  [128][264] f32(tf32)
#define ZPP 132   // z  [32][132]  f32(tf32)
#define TTP 257   // t  [32][257]  f32
#define UP  260   // u  [32][260]  f32
#define NPP 136   // Npacked [128][136] u32 (bf16x2)
#define SPP 264   // s  [32][264]  f32

__device__ float g_M[CZ*HC];
__device__ float g_N[HC*CZ];
__device__ float g_S[(size_t)NP*HC];

// ---------------------------------------------------------------------------
__device__ __forceinline__ uint32_t f2tf32(float x) {
    uint32_t r;
    asm("cvt.rna.tf32.f32 %0, %1;" : "=r"(r) : "f"(x));
    return r;
}

__device__ __forceinline__ void mma_tf32(float c[4], uint32_t a0, uint32_t a1,
                                         uint32_t a2, uint32_t a3,
                                         uint32_t b0, uint32_t b1) {
    asm volatile(
        "mma.sync.aligned.m16n8k8.row.col.f32.tf32.tf32.f32 "
        "{%0,%1,%2,%3}, {%4,%5,%6,%7}, {%8,%9}, {%0,%1,%2,%3};"
        : "+f"(c[0]), "+f"(c[1]), "+f"(c[2]), "+f"(c[3])
        : "r"(a0), "r"(a1), "r"(a2), "r"(a3), "r"(b0), "r"(b1));
}

__device__ __forceinline__ void mma_bf16(float c[4], uint32_t a0, uint32_t a1,
                                         uint32_t a2, uint32_t a3,
                                         uint32_t b0, uint32_t b1) {
    asm volatile(
        "mma.sync.aligned.m16n8k16.row.col.f32.bf16.bf16.f32 "
        "{%0,%1,%2,%3}, {%4,%5,%6,%7}, {%8,%9}, {%0,%1,%2,%3};"
        : "+f"(c[0]), "+f"(c[1]), "+f"(c[2]), "+f"(c[3])
        : "r"(a0), "r"(a1), "r"(a2), "r"(a3), "r"(b0), "r"(b1));
}

__device__ __forceinline__ uint32_t pack_bf2(float lo_elem, float hi_elem) {
    __nv_bfloat162 h = __floats2bfloat162_rn(lo_elem, hi_elem); // .x -> low 16
    return *reinterpret_cast<uint32_t*>(&h);
}

// ---------------------------------------------------------------------------
// K0: fold weights (unchanged from R1 — correct & cheap)
// ---------------------------------------------------------------------------
__global__ void fold_k(const float* __restrict__ Wq, const float* __restrict__ Wk,
                       const float* __restrict__ Wv, const float* __restrict__ Wo) {
    int idx = blockIdx.x * 256 + threadIdx.x;
    if (idx < CZ*HC) {
        int i = idx >> 8, hc = idx & 255;
        int h = hc >> 6, j = hc & 63;
        const float* wq = Wq + i*HC + h*64;
        const float* wk = Wk + j*HC + h*64;
        float a = 0.f;
        #pragma unroll
        for (int c = 0; c < 64; c++) a += wq[c] * wk[c];
        g_M[idx] = a * 0.125f;
    } else {
        int idx2 = idx - CZ*HC;
        int jh = idx2 >> 7, o = idx2 & 127;
        int h = jh >> 6, j = jh & 63;
        const float* wv = Wv + j*HC + h*64;
        const float* wo = Wo + (h*64)*CZ + o;
        float a = 0.f;
        #pragma unroll
        for (int c = 0; c < 64; c++) a += wv[c] * wo[c*CZ];
        g_N[idx2] = a;
    }
}

// ---------------------------------------------------------------------------
// K1: u = z @ M via tf32 mma ; softmax ; s -> g_S
// 256 threads = 8 warps: warp tile 16(m) x 64(n); warps 2(m) x 4(n).
// ---------------------------------------------------------------------------
__global__ __launch_bounds__(256, 1) void attn_k1(const float* __restrict__ z2d,
                                                  const float* __restrict__ t2d) {
    extern __shared__ float sm[];
    float* Ms = sm;                    // 128*264
    float* zs = Ms + CZ*MP;            // 32*132
    float* tt = zs + PB*ZPP;           // 32*257
    float* us = tt + PB*TTP;           // 32*260
    float* ws = us + PB*UP;            // 32*16
    const int tid = threadIdx.x;
    const int warp = tid >> 5, lane = tid & 31;
    const int g = lane >> 2, tig = lane & 3;
    const int wm = warp & 1, wn = warp >> 1;

    // stationary M (tf32-rounded)
    for (int k = tid; k < CZ*HC; k += 256) {
        int i = k >> 8, n = k & 255;
        Ms[i*MP + n] = __uint_as_float(f2tf32(g_M[k]));
    }

    for (int tl = 0; tl < TILES_PER_CTA; ++tl) {
        const int p0 = (blockIdx.x * TILES_PER_CTA + tl) * PB;

        // z tile (tf32-rounded), [p][i]
        for (int k = tid; k < PB*CZ; k += 256) {
            int p = k >> 7, i = k & 127;
            zs[p*ZPP + i] = __uint_as_float(f2tf32(z2d[(size_t)(p0 + p)*CZ + i]));
        }
        // template tile fp32: tt[p][t*64+j]
        for (int k = tid; k < PB*NT*64; k += 256) {
            int p = k >> 8, rem = k & 255;
            tt[p*TTP + rem] = t2d[((size_t)(rem >> 6)*NP + (p0 + p))*64 + (rem & 63)];
        }
        __syncthreads();

        // GEMM1: u[32][256] = z[32][128] @ M[128][256]
        float c[8][4];
        #pragma unroll
        for (int n8 = 0; n8 < 8; n8++)
            #pragma unroll
            for (int q = 0; q < 4; q++) c[n8][q] = 0.f;

        #pragma unroll
        for (int k8 = 0; k8 < 16; k8++) {
            const int k0 = k8 * 8;
            const int r0 = wm*16 + g;
            uint32_t a0 = __float_as_uint(zs[r0*ZPP + k0 + tig]);
            uint32_t a1 = __float_as_uint(zs[(r0+8)*ZPP + k0 + tig]);
            uint32_t a2 = __float_as_uint(zs[r0*ZPP + k0 + tig + 4]);
            uint32_t a3 = __float_as_uint(zs[(r0+8)*ZPP + k0 + tig + 4]);
            #pragma unroll
            for (int n8 = 0; n8 < 8; n8++) {
                const int n = wn*64 + n8*8 + g;
                uint32_t b0 = __float_as_uint(Ms[(k0 + tig)*MP + n]);
                uint32_t b1 = __float_as_uint(Ms[(k0 + tig + 4)*MP + n]);
                mma_tf32(c[n8], a0, a1, a2, a3, b0, b1);
            }
        }
        // store u fragments
        {
            const int r0 = wm*16 + g;
            #pragma unroll
            for (int n8 = 0; n8 < 8; n8++) {
                const int ncol = wn*64 + n8*8 + 2*tig;
                *(float2*)(us + r0*UP + ncol)     = make_float2(c[n8][0], c[n8][1]);
                *(float2*)(us + (r0+8)*UP + ncol) = make_float2(c[n8][2], c[n8][3]);
            }
        }
        __syncthreads();

        // logits + softmax (fp32 exact)
        if (tid < 128) {
            int h = tid >> 5, p = tid & 31;
            const float* up = us + p*UP + h*64;
            float lg[NT];
            #pragma unroll
            for (int t = 0; t < NT; t++) {
                const float* tp = tt + p*TTP + t*64;
                float a = 0.f;
                #pragma unroll
                for (int jj = 0; jj < 64; jj++) a += up[jj] * tp[jj];
                lg[t] = a;
            }
            float mx = fmaxf(fmaxf(lg[0], lg[1]), fmaxf(lg[2], lg[3]));
            float e0 = __expf(lg[0]-mx), e1 = __expf(lg[1]-mx);
            float e2 = __expf(lg[2]-mx), e3 = __expf(lg[3]-mx);
            float inv = 1.f / (e0 + e1 + e2 + e3);
            float* wp = ws + p*16 + h*4;
            wp[0] = e0*inv; wp[1] = e1*inv; wp[2] = e2*inv; wp[3] = e3*inv;
        }
        __syncthreads();

        // s (fp32 exact) -> g_S
        {
            const int h = tid >> 6, jj = tid & 63;
            #pragma unroll 4
            for (int p = 0; p < PB; p++) {
                const float* wp = ws + p*16 + h*4;
                const float* tp = tt + p*TTP + jj;
                float s = wp[0]*tp[0] + wp[1]*tp[64] + wp[2]*tp[128] + wp[3]*tp[192];
                g_S[(size_t)(p0 + p)*HC + tid] = s;
            }
        }
        __syncthreads();
    }
}

// ---------------------------------------------------------------------------
// K2: out = S @ N + bo via bf16 hi/lo (3 mma terms).
// 256 threads = 8 warps: warp tile 16(m) x 32(n); warps 2(m) x 4(n).
// N packed in smem as bf16x2 pairs along k: Npk[k/2][o].
// ---------------------------------------------------------------------------
__global__ __launch_bounds__(256, 1) void attn_k2(const float* __restrict__ bo,
                                                  float* __restrict__ out) {
    extern __shared__ float sm[];
    uint32_t* Nhi = (uint32_t*)sm;          // [128][136] u32
    uint32_t* Nlo = Nhi + 128*NPP;          // [128][136] u32
    float*    ss  = (float*)(Nlo + 128*NPP); // [32][264]
    const int tid = threadIdx.x;
    const int warp = tid >> 5, lane = tid & 31;
    const int g = lane >> 2, tig = lane & 3;
    const int wm = warp & 1, wn = warp >> 1;

    // stationary N, split+packed
    for (int k = tid; k < 128*CZ; k += 256) {
        int k2 = k >> 7, o = k & 127;
        float v0 = g_N[(size_t)(2*k2)*CZ + o];
        float v1 = g_N[(size_t)(2*k2 + 1)*CZ + o];
        float h0 = __bfloat162float(__float2bfloat16_rn(v0));
        float h1 = __bfloat162float(__float2bfloat16_rn(v1));
        Nhi[k2*NPP + o] = pack_bf2(h0, h1);
        Nlo[k2*NPP + o] = pack_bf2(v0 - h0, v1 - h1);
    }

    // per-thread bias for output columns
    float bias[4][2];
    #pragma unroll
    for (int n8 = 0; n8 < 4; n8++) {
        int ncol = wn*32 + n8*8 + 2*tig;
        bias[n8][0] = __ldg(bo + ncol);
        bias[n8][1] = __ldg(bo + ncol + 1);
    }

    for (int tl = 0; tl < TILES_PER_CTA; ++tl) {
        const int p0 = (blockIdx.x * TILES_PER_CTA + tl) * PB;
        for (int k = tid; k < PB*HC; k += 256) {
            int p = k >> 8, j = k & 255;
            ss[p*SPP + j] = g_S[(size_t)(p0 + p)*HC + j];
        }
        __syncthreads();

        float c[4][4];
        #pragma unroll
        for (int n8 = 0; n8 < 4; n8++)
            #pragma unroll
            for (int q = 0; q < 4; q++) c[n8][q] = 0.f;

        #pragma unroll
        for (int k16 = 0; k16 < 16; k16++) {
            const int k0 = k16 * 16;
            const int r0 = wm*16 + g;
            // A build: fp32 s -> bf16 hi/lo fragments
            float2 v00 = *(const float2*)(ss + r0*SPP + k0 + 2*tig);
            float2 v02 = *(const float2*)(ss + r0*SPP + k0 + 2*tig + 8);
            float2 v10 = *(const float2*)(ss + (r0+8)*SPP + k0 + 2*tig);
            float2 v12 = *(const float2*)(ss + (r0+8)*SPP + k0 + 2*tig + 8);
            float h00x = __bfloat162float(__float2bfloat16_rn(v00.x));
            float h00y = __bfloat162float(__float2bfloat16_rn(v00.y));
            float h02x = __bfloat162float(__float2bfloat16_rn(v02.x));
            float h02y = __bfloat162float(__float2bfloat16_rn(v02.y));
            float h10x = __bfloat162float(__float2bfloat16_rn(v10.x));
            float h10y = __bfloat162float(__float2bfloat16_rn(v10.y));
            float h12x = __bfloat162float(__float2bfloat16_rn(v12.x));
            float h12y = __bfloat162float(__float2bfloat16_rn(v12.y));
            uint32_t ah0 = pack_bf2(h00x, h00y);
            uint32_t ah1 = pack_bf2(h10x, h10y);
            uint32_t ah2 = pack_bf2(h02x, h02y);
            uint32_t ah3 = pack_bf2(h12x, h12y);
            uint32_t al0 = pack_bf2(v00.x - h00x, v00.y - h00y);
            uint32_t al1 = pack_bf2(v10.x - h10x, v10.y - h10y);
            uint32_t al2 = pack_bf2(v02.x - h02x, v02.y - h02y);
            uint32_t al3 = pack_bf2(v12.x - h12x, v12.y - h12y);

            const int kr = k0 / 2;   // packed row base
            #pragma unroll
            for (int n8 = 0; n8 < 4; n8++) {
                const int n = wn*32 + n8*8 + g;
                uint32_t bh0 = Nhi[(kr + tig)*NPP + n];
                uint32_t bh1 = Nhi[(kr + tig + 4)*NPP + n];
                uint32_t bl0 = Nlo[(kr + tig)*NPP + n];
                uint32_t bl1 = Nlo[(kr + tig + 4)*NPP + n];
                mma_bf16(c[n8], ah0, ah1, ah2, ah3, bh0, bh1); // s_hi * N_hi
                mma_bf16(c[n8], ah0, ah1, ah2, ah3, bl0, bl1); // s_hi * N_lo
                mma_bf16(c[n8], al0, al1, al2, al3, bh0, bh1); // s_lo * N_hi
            }
        }

        // epilogue: +bias, store
        {
            const int r0 = wm*16 + g;
            #pragma unroll
            for (int n8 = 0; n8 < 4; n8++) {
                const int ncol = wn*32 + n8*8 + 2*tig;
                *(float2*)(out + (size_t)(p0 + r0)*CZ + ncol) =
                    make_float2(c[n8][0] + bias[n8][0], c[n8][1] + bias[n8][1]);
                *(float2*)(out + (size_t)(p0 + r0 + 8)*CZ + ncol) =
                    make_float2(c[n8][2] + bias[n8][0], c[n8][3] + bias[n8][1]);
            }
        }
        __syncthreads();
    }
}

// ---------------------------------------------------------------------------
extern "C" void kernel_launch(void* const* d_in, const int* in_sizes, int n_in,
                              void* d_out, int out_size) {
    const float* z2d = (const float*)d_in[0];
    const float* t2d = (const float*)d_in[1];
    const float* Wq  = (const float*)d_in[2];
    const float* Wk  = (const float*)d_in[3];
    const float* Wv  = (const float*)d_in[4];
    const float* Wo  = (const float*)d_in[5];
    const float* Wo2 = (const float*)d_in[5];
    const float* bo  = (const float*)d_in[6];
    (void)Wo2;
    float* out = (float*)d_out;

    const size_t sm1 = (size_t)(CZ*MP + PB*ZPP + PB*TTP + PB*UP + PB*16) * sizeof(float);
    const size_t sm2 = (size_t)(128*NPP*2) * sizeof(uint32_t) + (size_t)(PB*SPP) * sizeof(float);
    cudaFuncSetAttribute(attn_k1, cudaFuncAttributeMaxDynamicSharedMemorySize, (int)sm1);
    cudaFuncSetAttribute(attn_k2, cudaFuncAttributeMaxDynamicSharedMemorySize, (int)sm2);

    fold_k<<<256, 256>>>(Wq, Wk, Wv, Wo);
    attn_k1<<<GRID1, 256, sm1>>>(z2d, t2d);
    attn_k2<<<GRID1, 256, sm2>>>(bo, out);
}